// round 4
// baseline (speedup 1.0000x reference)
#include <cuda_runtime.h>

// Problem dims
#define BB 16
#define TT 64
#define LL 512
#define CC 64
#define HH 150
#define G3 450   // 3*H

// Tiling
#define TILE_L 64
#define TILE_J 64
#define KKC 32
#define NTHREADS 256

// x slab uses padded row stride 65 (64 would be a 16-way smem bank conflict
// for the sliding-window A reads: stride 64 mod 32 banks == 0).
#define CXP 65
#define KXP (5*CXP)            // 325 logical padded K for x-phase
#define KXCHUNKS 11            // ceil(325/32) -> covers 352 with zero weights
#define KHCHUNKS 24            // ceil(750/32) -> covers 768 with zero weights

#define SLAB_H ((TILE_L+4)*HH + 32)   // +32 zero pad: a-reads go to k up to 767
#define SLAB_X ((TILE_L+4)*CXP + 32)  // +32 zero pad: a-reads go to k' up to 351
#define WTILE  (KKC*TILE_J)

// Scratch (device globals: no allocation allowed)
__device__ float g_h[BB*LL*HH];          // hidden state, 4.9 MB
__device__ float g_gates[BB*LL*600];     // [0,300): gi+gh (r,z); [300,450): gi_n; [450,600): gh_n

__global__ void zero_h_kernel() {
    int i = blockIdx.x * blockDim.x + threadIdx.x;
    if (i < BB*LL*HH) g_h[i] = 0.f;
}

extern __shared__ float smem[];

// One recurrent step: gi = conv(xs[:,t], ki), gh = conv(h, kh), write gate pre-activations.
__global__ __launch_bounds__(NTHREADS) void step_kernel(
    const float* __restrict__ xs,
    const float* __restrict__ ki,
    const float* __restrict__ kh,
    int t)
{
    float* sh_h = smem;                 // SLAB_H floats
    float* sh_x = sh_h + SLAB_H;        // SLAB_X floats
    float* sh_w = sh_x + SLAB_X;        // WTILE floats

    const int jt  = blockIdx.x;         // 0..7  (j tile)
    const int l0  = blockIdx.y * TILE_L;// 0..7 * 64
    const int b   = blockIdx.z;         // 0..15
    const int j0  = jt * TILE_J;
    const int tid = threadIdx.x;
    const int lt  = tid & 15;           // l-thread 0..15 (x4 strided rows)
    const int jq  = tid >> 4;           // j-thread 0..15 (x4 contiguous cols)

    // ---- load h slab: rows [l0-2, l0+TILE_L+2), stride HH ----
    for (int idx = tid; idx < SLAB_H; idx += NTHREADS) {
        float v = 0.f;
        if (idx < (TILE_L+4)*HH) {
            int r = idx / HH, m = idx - r*HH;
            int lg = l0 - 2 + r;
            if (lg >= 0 && lg < LL) v = g_h[(b*LL + lg)*HH + m];
        }
        sh_h[idx] = v;
    }
    // ---- load x slab: rows [l0-2, l0+TILE_L+2), padded stride CXP ----
    const float* xs_bt = xs + ((size_t)(b*TT + t)) * (LL*CC);
    for (int idx = tid; idx < SLAB_X; idx += NTHREADS) {
        float v = 0.f;
        if (idx < (TILE_L+4)*CXP) {
            int r = idx / CXP, c = idx - r*CXP;
            int lg = l0 - 2 + r;
            if (c < CC && lg >= 0 && lg < LL) v = xs_bt[lg*CC + c];
        }
        sh_x[idx] = v;
    }
    __syncthreads();

    float acc_i[4][4], acc_h[4][4];
#pragma unroll
    for (int i = 0; i < 4; i++)
#pragma unroll
        for (int j = 0; j < 4; j++) { acc_i[i][j] = 0.f; acc_h[i][j] = 0.f; }

    // ================= Phase X: gi, K' = 325 (padded-stride k' = d*65 + c) ==========
    for (int ch = 0; ch < KXCHUNKS; ch++) {
        const int kc = ch * KKC;
        for (int idx = tid; idx < WTILE; idx += NTHREADS) {
            int kk = idx >> 6, jj = idx & 63;
            int kg = kc + kk;
            int d = kg / CXP, c = kg - d*CXP;
            int jg = j0 + jj;
            float w = 0.f;
            if (d < 5 && c < CC && jg < G3) w = ki[(d*CC + c)*G3 + jg];
            sh_w[idx] = w;
        }
        __syncthreads();
#pragma unroll
        for (int kk = 0; kk < KKC; kk++) {
            const int kg = kc + kk;
            float a[4];
            a[0] = sh_x[(lt     )*CXP + kg];
            a[1] = sh_x[(lt + 16)*CXP + kg];
            a[2] = sh_x[(lt + 32)*CXP + kg];
            a[3] = sh_x[(lt + 48)*CXP + kg];
            const float4 wv = *(const float4*)(sh_w + kk*TILE_J + (jq << 2));
            const float w[4] = {wv.x, wv.y, wv.z, wv.w};
#pragma unroll
            for (int i = 0; i < 4; i++)
#pragma unroll
                for (int j = 0; j < 4; j++) acc_i[i][j] += a[i] * w[j];
        }
        __syncthreads();
    }

    // ================= Phase H: gh, K = 750 (k = d*150 + m) =========================
    for (int ch = 0; ch < KHCHUNKS; ch++) {
        const int kc = ch * KKC;
        for (int idx = tid; idx < WTILE; idx += NTHREADS) {
            int kk = idx >> 6, jj = idx & 63;
            int kg = kc + kk;
            int jg = j0 + jj;
            float w = 0.f;
            if (kg < 5*HH && jg < G3) w = kh[kg*G3 + jg];
            sh_w[idx] = w;
        }
        __syncthreads();
#pragma unroll
        for (int kk = 0; kk < KKC; kk++) {
            const int kg = kc + kk;
            float a[4];
            a[0] = sh_h[(lt     )*HH + kg];
            a[1] = sh_h[(lt + 16)*HH + kg];
            a[2] = sh_h[(lt + 32)*HH + kg];
            a[3] = sh_h[(lt + 48)*HH + kg];
            const float4 wv = *(const float4*)(sh_w + kk*TILE_J + (jq << 2));
            const float w[4] = {wv.x, wv.y, wv.z, wv.w};
#pragma unroll
            for (int i = 0; i < 4; i++)
#pragma unroll
                for (int j = 0; j < 4; j++) acc_h[i][j] += a[i] * w[j];
        }
        __syncthreads();
    }

    // ---- store gate pre-activations ----
#pragma unroll
    for (int i = 0; i < 4; i++) {
        const int lg = l0 + lt + 16*i;
        float* grow = g_gates + (size_t)(b*LL + lg) * 600;
#pragma unroll
        for (int jj = 0; jj < 4; jj++) {
            const int j = j0 + (jq << 2) + jj;
            if (j < 300) {
                grow[j] = acc_i[i][jj] + acc_h[i][jj];
            } else if (j < G3) {
                grow[j]       = acc_i[i][jj];   // iin
                grow[j + 150] = acc_h[i][jj];   // hin
            }
        }
    }
}

// GRU gate update: h = (1-z)*n + z*h
__global__ void gate_kernel() {
    int idx = blockIdx.x * blockDim.x + threadIdx.x;
    if (idx >= BB*LL*HH) return;
    int bl = idx / HH;
    int m  = idx - bl*HH;
    const float* G = g_gates + (size_t)bl * 600;
    float r = 1.f / (1.f + __expf(-G[m]));
    float z = 1.f / (1.f + __expf(-(G[150 + m])));
    float n = tanhf(G[300 + m] + r * G[450 + m]);
    float h = g_h[idx];
    g_h[idx] = (1.f - z) * n + z * h;
}

// Head: hdn = silu(h @ W1 + b1); out = hdn @ W2 + b2
__global__ void head_kernel(const float* __restrict__ W1, const float* __restrict__ b1,
                            const float* __restrict__ W2, const float* __restrict__ b2,
                            float* __restrict__ out)
{
    __shared__ float hv[HH];
    __shared__ float hd[HH];
    const int bl  = blockIdx.x;          // 0 .. B*L-1
    const int tid = threadIdx.x;
    if (tid < HH) hv[tid] = g_h[(size_t)bl*HH + tid];
    __syncthreads();
    if (tid < HH) {
        float s = b1[tid];
#pragma unroll 5
        for (int m = 0; m < HH; m++) s += hv[m] * W1[m*HH + tid];
        hd[tid] = s / (1.f + __expf(-s));   // silu
    }
    __syncthreads();
    if (tid < 24) {
        float s = b2[tid];
#pragma unroll 5
        for (int m = 0; m < HH; m++) s += hd[m] * W2[m*24 + tid];
        out[(size_t)bl*24 + tid] = s;
    }
}

extern "C" void kernel_launch(void* const* d_in, const int* in_sizes, int n_in,
                              void* d_out, int out_size)
{
    const float* xs = (const float*)d_in[0];
    const float* ki = (const float*)d_in[1];
    const float* kh = (const float*)d_in[2];
    const float* W1 = (const float*)d_in[3];
    const float* b1 = (const float*)d_in[4];
    const float* W2 = (const float*)d_in[5];
    const float* b2 = (const float*)d_in[6];
    float* out = (float*)d_out;

    const int smem_bytes = (SLAB_H + SLAB_X + WTILE) * (int)sizeof(float);
    cudaFuncSetAttribute(step_kernel, cudaFuncAttributeMaxDynamicSharedMemorySize, smem_bytes);

    zero_h_kernel<<<(BB*LL*HH + 255)/256, 256>>>();

    dim3 grid(8, LL/TILE_L, BB);   // j-tiles x l-tiles x batch
    for (int t = 0; t < TT; t++) {
        step_kernel<<<grid, NTHREADS, smem_bytes>>>(xs, ki, kh, t);
        gate_kernel<<<(BB*LL*HH + 255)/256, 256>>>();
    }

    head_kernel<<<BB*LL, 160>>>(W1, b1, W2, b2, out);
}

// round 10
// speedup vs baseline: 5.4998x; 5.4998x over previous
#include <cuda_runtime.h>
#include <cuda_bf16.h>
#include <cstdint>

// ---------------- problem dims ----------------
#define BB 16
#define TT 64
#define LL 512
#define CC 64
#define HH 150
#define G3 450
#define HP 160            // padded h channels (10 k16-chunks per tap)

// K-chunk counts (k16 chunks)
#define XCH 20            // 5 taps * 4
#define HCH 50            // 5 taps * 10

// slab geometry
#define SLAB_ROWS 132     // 128 + 4 halo
#define RBX 128           // x slab row bytes (64 bf16)
#define RBH 384           // h slab row bytes (160 bf16 -> 24 units padded)
#define SLABX_B (SLAB_ROWS*RBX)   // 16896
#define SLABH_B (SLAB_ROWS*RBH)   // 50688
#define SM_TOTAL (2*SLABX_B + 2*SLABH_B)  // 135168

// ---------------- device scratch ----------------
__device__ float          g_h[BB*LL*HH];
__device__ __nv_bfloat16  g_h_hi[BB*LL*HP];
__device__ __nv_bfloat16  g_h_lo[BB*LL*HP];
__device__ __nv_bfloat16  g_xs_hi[(size_t)BB*TT*LL*CC];
__device__ __nv_bfloat16  g_xs_lo[(size_t)BB*TT*LL*CC];
__device__ float          g_gates[BB*LL*600];
// B in mma-fragment layout: [chunk][n16(32)][lane(32)] uint4
__device__ uint4          g_bx_hi[XCH*32*32];
__device__ uint4          g_bx_lo[XCH*32*32];
__device__ uint4          g_bh_hi[HCH*32*32];
__device__ uint4          g_bh_lo[HCH*32*32];

// ---------------- helpers ----------------
__device__ __forceinline__ uint32_t smem_u32(const void* p) {
    uint32_t a;
    asm("{ .reg .u64 t; cvta.to.shared.u64 t, %1; cvt.u32.u64 %0, t; }" : "=r"(a) : "l"(p));
    return a;
}
__device__ __forceinline__ void ldsm4(uint32_t a[4], uint32_t addr) {
    asm volatile("ldmatrix.sync.aligned.m8n8.x4.shared.b16 {%0,%1,%2,%3}, [%4];"
                 : "=r"(a[0]), "=r"(a[1]), "=r"(a[2]), "=r"(a[3]) : "r"(addr));
}
__device__ __forceinline__ void mma_bf16(float c[4], const uint32_t a[4], uint32_t b0, uint32_t b1) {
    asm volatile("mma.sync.aligned.m16n8k16.row.col.f32.bf16.bf16.f32 "
                 "{%0,%1,%2,%3}, {%4,%5,%6,%7}, {%8,%9}, {%0,%1,%2,%3};"
                 : "+f"(c[0]), "+f"(c[1]), "+f"(c[2]), "+f"(c[3])
                 : "r"(a[0]), "r"(a[1]), "r"(a[2]), "r"(a[3]), "r"(b0), "r"(b1));
}
__device__ __forceinline__ uint32_t pack_bf2(float a, float b) {
    uint32_t lo = __bfloat16_as_ushort(__float2bfloat16(a));
    uint32_t hi = __bfloat16_as_ushort(__float2bfloat16(b));
    return lo | (hi << 16);
}

// ---------------- prep kernels ----------------
__global__ void init_h_kernel() {
    int i = blockIdx.x * blockDim.x + threadIdx.x;
    if (i < BB*LL*HH) g_h[i] = 0.f;
    if (i < BB*LL*HP) { g_h_hi[i] = __float2bfloat16(0.f); g_h_lo[i] = __float2bfloat16(0.f); }
}
__global__ void xs_split_kernel(const float* __restrict__ xs) {
    size_t i = (size_t)blockIdx.x * blockDim.x + threadIdx.x;
    if (i >= (size_t)BB*TT*LL*CC) return;
    float v = xs[i];
    __nv_bfloat16 hi = __float2bfloat16(v);
    g_xs_hi[i] = hi;
    g_xs_lo[i] = __float2bfloat16(v - __bfloat162float(hi));
}
// pack ki into fragment layout: k = d*64 + c, K=320
__global__ void bx_prep_kernel(const float* __restrict__ ki) {
    int idx = blockIdx.x * blockDim.x + threadIdx.x;
    if (idx >= XCH*32*32) return;
    int lane = idx & 31, n16 = (idx >> 5) & 31, ch = idx >> 10;
    int k0 = ch*16 + (lane & 3)*2;
    int na = n16*16 + (lane >> 2);
    float w[8];
#pragma unroll
    for (int h = 0; h < 2; h++) {
        int j = na + h*8;
#pragma unroll
        for (int kk = 0; kk < 4; kk++) {
            int k = k0 + (kk >> 1)*8 + (kk & 1);
            int d = k >> 6, c = k & 63;
            w[h*4 + kk] = (j < G3) ? ki[(d*CC + c)*G3 + j] : 0.f;
        }
    }
    float whi[8], wlo[8];
#pragma unroll
    for (int q = 0; q < 8; q++) {
        float hv = __bfloat162float(__float2bfloat16(w[q]));
        whi[q] = hv; wlo[q] = w[q] - hv;
    }
    g_bx_hi[idx] = make_uint4(pack_bf2(whi[0],whi[1]), pack_bf2(whi[2],whi[3]),
                              pack_bf2(whi[4],whi[5]), pack_bf2(whi[6],whi[7]));
    g_bx_lo[idx] = make_uint4(pack_bf2(wlo[0],wlo[1]), pack_bf2(wlo[2],wlo[3]),
                              pack_bf2(wlo[4],wlo[5]), pack_bf2(wlo[6],wlo[7]));
}
// pack kh: k = d*160 + m, K=800
__global__ void bh_prep_kernel(const float* __restrict__ kh) {
    int idx = blockIdx.x * blockDim.x + threadIdx.x;
    if (idx >= HCH*32*32) return;
    int lane = idx & 31, n16 = (idx >> 5) & 31, ch = idx >> 10;
    int k0 = ch*16 + (lane & 3)*2;
    int na = n16*16 + (lane >> 2);
    float w[8];
#pragma unroll
    for (int h = 0; h < 2; h++) {
        int j = na + h*8;
#pragma unroll
        for (int kk = 0; kk < 4; kk++) {
            int k = k0 + (kk >> 1)*8 + (kk & 1);
            int d = k / HP, m = k - d*HP;
            w[h*4 + kk] = (j < G3 && m < HH) ? kh[(d*HH + m)*G3 + j] : 0.f;
        }
    }
    float whi[8], wlo[8];
#pragma unroll
    for (int q = 0; q < 8; q++) {
        float hv = __bfloat162float(__float2bfloat16(w[q]));
        whi[q] = hv; wlo[q] = w[q] - hv;
    }
    g_bh_hi[idx] = make_uint4(pack_bf2(whi[0],whi[1]), pack_bf2(whi[2],whi[3]),
                              pack_bf2(whi[4],whi[5]), pack_bf2(whi[6],whi[7]));
    g_bh_lo[idx] = make_uint4(pack_bf2(wlo[0],wlo[1]), pack_bf2(wlo[2],wlo[3]),
                              pack_bf2(wlo[4],wlo[5]), pack_bf2(wlo[6],wlo[7]));
}

// ---------------- the GEMM phase ----------------
// One phase = one conv (x or h) for one n16 tile. A from swizzled smem slabs,
// B from fragment-packed global, 3 split passes (hi*hi + hi*lo + lo*hi).
template<int CPT, int RB>
__device__ __forceinline__ void run_phase(
    uint32_t sbh, uint32_t sbl,                 // smem bases: A hi / A lo
    const uint4* __restrict__ Bh, const uint4* __restrict__ Bl,
    float* acc, int n16g, int lane)
{
    const int rlow = lane & 15;
    const int r2   = lane >> 4;
    const uint4* bh_p = Bh + n16g*32 + lane;
    const uint4* bl_p = Bl + n16g*32 + lane;
#pragma unroll 1
    for (int d = 0; d < 5; d++) {
#pragma unroll 1
        for (int cs = 0; cs < CPT; cs++) {
            const uint4 bh = *bh_p;  bh_p += 1024;
            const uint4 bl = *bl_p;  bl_p += 1024;
            const int lu = cs*2 + r2;
#pragma unroll
            for (int mg = 0; mg < 2; mg++) {
                uint32_t ah[4][4], al[4][4];
#pragma unroll
                for (int q = 0; q < 4; q++) {
                    const int mt  = mg*4 + q;
                    const int row = d + mt*16 + rlow;
                    const uint32_t off = row*RB + (((lu ^ row) & 7) << 4) + ((lu & ~7) << 4);
                    ldsm4(ah[q], sbh + off);
                    ldsm4(al[q], sbl + off);
                }
#pragma unroll
                for (int q = 0; q < 4; q++) {
                    float* A0 = acc + (mg*4 + q)*8;
                    float* A1 = A0 + 4;
                    mma_bf16(A0, ah[q], bh.x, bh.y);
                    mma_bf16(A1, ah[q], bh.z, bh.w);
                    mma_bf16(A0, ah[q], bl.x, bl.y);
                    mma_bf16(A1, ah[q], bl.z, bl.w);
                    mma_bf16(A0, al[q], bh.x, bh.y);
                    mma_bf16(A1, al[q], bh.z, bh.w);
                }
            }
        }
    }
}

// ---------------- step kernel ----------------
__global__ __launch_bounds__(256, 1) void step_mma_kernel(int t)
{
    extern __shared__ char smem[];
    char* sxh = smem;
    char* sxl = smem + SLABX_B;
    char* shh = smem + 2*SLABX_B;
    char* shl = shh + SLABH_B;

    const int tid  = threadIdx.x;
    const int lane = tid & 31;
    const int wid  = tid >> 5;
    const int jhalf = blockIdx.x;          // 0..1
    const int mtb   = blockIdx.y;          // 0..63
    const int b  = mtb >> 2;
    const int l0 = (mtb & 3) * 128;

    // ---- fill x slab (hi+lo), swizzled: unit lu stored at lu^(row&7) ----
    for (int i = tid; i < SLAB_ROWS*8; i += 256) {
        const int s = i >> 3, lu = i & 7;
        const int lg = l0 - 2 + s;
        uint4 vh = make_uint4(0,0,0,0), vl = make_uint4(0,0,0,0);
        if (lg >= 0 && lg < LL) {
            const size_t base = ((size_t)(b*TT + t)*LL + lg)*CC + lu*8;
            vh = *(const uint4*)(g_xs_hi + base);
            vl = *(const uint4*)(g_xs_lo + base);
        }
        const int off = s*RBX + (((lu ^ s) & 7) << 4);
        *(uint4*)(sxh + off) = vh;
        *(uint4*)(sxl + off) = vl;
    }
    // ---- fill h slab (hi+lo), 20 units/row, padded row 24 units ----
    for (int i = tid; i < SLAB_ROWS*20; i += 256) {
        const int s = i / 20, lu = i - s*20;
        const int lg = l0 - 2 + s;
        uint4 vh = make_uint4(0,0,0,0), vl = make_uint4(0,0,0,0);
        if (lg >= 0 && lg < LL) {
            const size_t base = ((size_t)(b*LL + lg))*HP + lu*8;
            vh = *(const uint4*)(g_h_hi + base);
            vl = *(const uint4*)(g_h_lo + base);
        }
        const int off = s*RBH + ((lu & ~7) << 4) + (((lu ^ s) & 7) << 4);
        *(uint4*)(shh + off) = vh;
        *(uint4*)(shl + off) = vl;
    }
    __syncthreads();

    // Two n16 tile-groups per warp -> full j coverage [0, 512) across the grid.
    // (R7 bug: only [0,256) was computed; j 256..449 were never written.)
#pragma unroll 1
    for (int g = 0; g < 2; g++) {
        const int n16g = jhalf*16 + g*8 + wid;   // 0..31
        if (n16g >= 29) continue;                // tiles 29..31 are pure zero padding

        float acc_i[64], acc_h[64];
#pragma unroll
        for (int q = 0; q < 64; q++) { acc_i[q] = 0.f; acc_h[q] = 0.f; }

        run_phase<4,  RBX>(smem_u32(sxh), smem_u32(sxl), g_bx_hi, g_bx_lo, acc_i, n16g, lane);
        run_phase<10, RBH>(smem_u32(shh), smem_u32(shl), g_bh_hi, g_bh_lo, acc_h, n16g, lane);

        // ---- epilogue: write gate pre-activations ----
        const int row_in = lane >> 2;
        const int col0   = (lane & 3)*2;
        const int jb     = n16g*16;
#pragma unroll
        for (int mt = 0; mt < 8; mt++) {
#pragma unroll
            for (int rr = 0; rr < 2; rr++) {
                const int l = l0 + mt*16 + row_in + rr*8;
                float* grow = g_gates + (size_t)(b*LL + l)*600;
#pragma unroll
                for (int n8 = 0; n8 < 2; n8++) {
#pragma unroll
                    for (int cc = 0; cc < 2; cc++) {
                        const int j  = jb + n8*8 + col0 + cc;
                        const float vi = acc_i[mt*8 + n8*4 + rr*2 + cc];
                        const float vh = acc_h[mt*8 + n8*4 + rr*2 + cc];
                        if (j < 300)      grow[j] = vi + vh;
                        else if (j < G3) { grow[j] = vi; grow[j + 150] = vh; }
                    }
                }
            }
        }
    }
}

// ---------------- GRU gate update ----------------
__global__ void gate_kernel() {
    int idx = blockIdx.x * blockDim.x + threadIdx.x;
    if (idx >= BB*LL*HH) return;
    int bl = idx / HH;
    int m  = idx - bl*HH;
    const float* G = g_gates + (size_t)bl * 600;
    float r = 1.f / (1.f + __expf(-G[m]));
    float z = 1.f / (1.f + __expf(-(G[150 + m])));
    float n = tanhf(G[300 + m] + r * G[450 + m]);
    float h = (1.f - z) * n + z * g_h[idx];
    g_h[idx] = h;
    __nv_bfloat16 hi = __float2bfloat16(h);
    g_h_hi[(size_t)bl*HP + m] = hi;
    g_h_lo[(size_t)bl*HP + m] = __float2bfloat16(h - __bfloat162float(hi));
}

// ---------------- head ----------------
__global__ void head_kernel(const float* __restrict__ W1, const float* __restrict__ b1,
                            const float* __restrict__ W2, const float* __restrict__ b2,
                            float* __restrict__ out)
{
    __shared__ float hv[HH];
    __shared__ float hd[HH];
    const int bl  = blockIdx.x;
    const int tid = threadIdx.x;
    if (tid < HH) hv[tid] = g_h[(size_t)bl*HH + tid];
    __syncthreads();
    if (tid < HH) {
        float s = b1[tid];
#pragma unroll 5
        for (int m = 0; m < HH; m++) s += hv[m] * W1[m*HH + tid];
        hd[tid] = s / (1.f + __expf(-s));
    }
    __syncthreads();
    if (tid < 24) {
        float s = b2[tid];
#pragma unroll 5
        for (int m = 0; m < HH; m++) s += hd[m] * W2[m*24 + tid];
        out[(size_t)bl*24 + tid] = s;
    }
}

extern "C" void kernel_launch(void* const* d_in, const int* in_sizes, int n_in,
                              void* d_out, int out_size)
{
    const float* xs = (const float*)d_in[0];
    const float* ki = (const float*)d_in[1];
    const float* kh = (const float*)d_in[2];
    const float* W1 = (const float*)d_in[3];
    const float* b1 = (const float*)d_in[4];
    const float* W2 = (const float*)d_in[5];
    const float* b2 = (const float*)d_in[6];
    float* out = (float*)d_out;

    cudaFuncSetAttribute(step_mma_kernel, cudaFuncAttributeMaxDynamicSharedMemorySize, SM_TOTAL);

    init_h_kernel<<<(BB*LL*HP + 255)/256, 256>>>();
    const size_t nxs = (size_t)BB*TT*LL*CC;
    xs_split_kernel<<<(unsigned)((nxs + 255)/256), 256>>>(xs);
    bx_prep_kernel<<<(XCH*32*32 + 255)/256, 256>>>(ki);
    bh_prep_kernel<<<(HCH*32*32 + 255)/256, 256>>>(kh);

    dim3 grid(2, 64);   // j-half x M-tiles
    for (int t = 0; t < TT; t++) {
        step_mma_kernel<<<grid, 256, SM_TOTAL>>>(t);
        gate_kernel<<<(BB*LL*HH + 255)/256, 256>>>();
    }

    head_kernel<<<BB*LL, 160>>>(W1, b1, W2, b2, out);
}